// round 17
// baseline (speedup 1.0000x reference)
#include <cuda_runtime.h>
#include <cuda_fp16.h>
#include <mma.h>
#include <math.h>
#include <stdint.h>

using namespace nvcuda;

#define Bv 16
#define Sv 2048
#define Ev 256
#define Lv 2
#define NQv 8
#define FFNv 512
#define Cv 2
#define Mv (Bv*Sv)   // 32768 token rows

// Scratch (static device allocations; no cudaMalloc allowed)
__device__ float  g_x[Mv*Ev];        // activations (in-place updated)
__device__ __half g_hh[Mv*FFNv];     // ffn hidden, fp16 hi
__device__ __half g_hl[Mv*FFNv];     // ffn hidden, fp16 lo (exact residual)
__device__ __half g_bth[Ev*FFNv];    // transposed B, fp16 (max 256x512)
__device__ float  g_pool[Bv*32*Ev];  // pool partials

// ---------------------------------------------------------------------------
// 1. embedding gather + sinusoidal positional encoding
// ---------------------------------------------------------------------------
__global__ void embed_pos_kernel(const int* __restrict__ tokens,
                                 const float* __restrict__ embed,
                                 float* __restrict__ x) {
    int idx = blockIdx.x * blockDim.x + threadIdx.x;
    if (idx >= Mv * Ev) return;
    int e   = idx & (Ev - 1);
    int row = idx >> 8;
    int s   = row & (Sv - 1);
    int tok = tokens[row];
    float i2 = (float)(e & ~1);
    float d  = expf(i2 * (-9.210340371976184f / 256.0f));
    float arg = (float)s * d;
    float pe = (e & 1) ? cosf(arg) : sinf(arg);
    x[idx] = embed[tok * Ev + e] + pe;
}

// ---------------------------------------------------------------------------
// 2a. prep: transpose B [K,N=256] -> Bt [N,K], round to fp16
// ---------------------------------------------------------------------------
__global__ void prep_bt_kernel(const float* __restrict__ B,
                               __half* __restrict__ bth, int K) {
    int idx = blockIdx.x * 256 + threadIdx.x;
    if (idx >= K * Ev) return;
    int k = idx >> 8, n = idx & 255;
    bth[(size_t)n * K + k] = __float2half_rn(B[idx]);
}

// ---------------------------------------------------------------------------
// 2b. wmma fp16 GEMM (A split exact hi+lo, B rounded) + fused residual+LN.
//     xnew[M,256] = LN( xres + op(A)@B + bias ) * g + b
//     MODE 1: A fp32, op(A)=cos(A+theta[k&63]), split on the fly
//     MODE 0: A pre-split half arrays Ah/Al
//     CTA tile 64x256, 256 threads = 8 warps (2x4), warp tile 32x64.
//     Register-prefetched mainloop; 2 CTAs/SM co-resident.
// ---------------------------------------------------------------------------
#define PADH 40                        // halfs per smem row (32 data + 8 pad)
#define SA_H (64*PADH)                 // 2560 halfs per A tile
#define LDC  260
#define SMEM_TOT (64*LDC*4)            // 66560 B (epilogue fp32 buffer is max)

template<int MODE>
__global__ void __launch_bounds__(256)
gemm_ln(const float* __restrict__ A,
        const __half* __restrict__ Ah, const __half* __restrict__ Al,
        const __half* __restrict__ Bt,
        const float* __restrict__ bias, const float* __restrict__ theta,
        const float* __restrict__ lng, const float* __restrict__ lnb,
        const float* __restrict__ xres, float* __restrict__ Cout, int K) {
    extern __shared__ char smem[];
    __half* sAh = (__half*)smem;                 // [64][PADH]
    __half* sAl = sAh + SA_H;                    // [64][PADH]
    __half* sBh = sAl + SA_H;                    // [256][PADH]

    const int t      = threadIdx.x;
    const int w      = t >> 5;
    const int lane   = t & 31;
    const int warp_m = w & 1;                    // 2 bands of 32 rows
    const int warp_n = w >> 1;                   // 4 bands of 64 cols
    const int row0   = blockIdx.x * 64;

    wmma::fragment<wmma::accumulator, 16, 16, 16, float> acc[2][4];
#pragma unroll
    for (int mi = 0; mi < 2; mi++)
#pragma unroll
        for (int ni = 0; ni < 4; ni++) wmma::fill_fragment(acc[mi][ni], 0.0f);

    const int rA = t >> 2, qA = t & 3;           // A: row 0..63, 8-elem group
    const int rB = t;                            // B: row 0..255, full 32 halfs

    const int nch = K >> 5;

    // ---- prefetch chunk 0 into registers ----
    float4 aF0, aF1;          // MODE 1
    uint4  aH, aL;            // MODE 0
    uint4  bR[4];
    {
        if (MODE == 1) {
            const float4* ar = (const float4*)(A + (size_t)(row0 + rA) * K + qA * 8);
            aF0 = ar[0]; aF1 = ar[1];
        } else {
            aH = *(const uint4*)(Ah + (size_t)(row0 + rA) * K + qA * 8);
            aL = *(const uint4*)(Al + (size_t)(row0 + rA) * K + qA * 8);
        }
        const uint4* bs = (const uint4*)(Bt + (size_t)rB * K);
#pragma unroll
        for (int q = 0; q < 4; q++) bR[q] = bs[q];
    }

    for (int ch = 0; ch < nch; ch++) {
        const int k0 = ch * 32;
        // ---- STS current chunk from registers ----
        if (MODE == 1) {
            float vv[8] = {aF0.x, aF0.y, aF0.z, aF0.w, aF1.x, aF1.y, aF1.z, aF1.w};
            __half hh[8], hl[8];
#pragma unroll
            for (int j = 0; j < 8; j++) {
                float f = cosf(vv[j] + theta[(k0 + qA * 8 + j) & 63]);
                __half hi = __float2half_rn(f);
                hh[j] = hi;
                hl[j] = __float2half_rn(f - __half2float(hi));
            }
            *(uint4*)(sAh + rA * PADH + qA * 8) = *(uint4*)hh;
            *(uint4*)(sAl + rA * PADH + qA * 8) = *(uint4*)hl;
        } else {
            *(uint4*)(sAh + rA * PADH + qA * 8) = aH;
            *(uint4*)(sAl + rA * PADH + qA * 8) = aL;
        }
        {
            uint4* bd = (uint4*)(sBh + rB * PADH);
#pragma unroll
            for (int q = 0; q < 4; q++) bd[q] = bR[q];
        }
        // ---- prefetch next chunk ----
        if (ch + 1 < nch) {
            const int k1 = k0 + 32;
            if (MODE == 1) {
                const float4* ar = (const float4*)(A + (size_t)(row0 + rA) * K + k1 + qA * 8);
                aF0 = ar[0]; aF1 = ar[1];
            } else {
                aH = *(const uint4*)(Ah + (size_t)(row0 + rA) * K + k1 + qA * 8);
                aL = *(const uint4*)(Al + (size_t)(row0 + rA) * K + k1 + qA * 8);
            }
            const uint4* bs = (const uint4*)(Bt + (size_t)rB * K + k1);
#pragma unroll
            for (int q = 0; q < 4; q++) bR[q] = bs[q];
        }
        __syncthreads();

#pragma unroll
        for (int kk = 0; kk < 2; kk++) {
            wmma::fragment<wmma::matrix_a, 16, 16, 16, __half, wmma::row_major> ah[2], al[2];
#pragma unroll
            for (int mi = 0; mi < 2; mi++) {
                const __half* ap = sAh + (warp_m * 32 + mi * 16) * PADH + kk * 16;
                const __half* lp = sAl + (warp_m * 32 + mi * 16) * PADH + kk * 16;
                wmma::load_matrix_sync(ah[mi], ap, PADH);
                wmma::load_matrix_sync(al[mi], lp, PADH);
            }
#pragma unroll
            for (int ni = 0; ni < 4; ni++) {
                wmma::fragment<wmma::matrix_b, 16, 16, 16, __half, wmma::col_major> bh;
                wmma::load_matrix_sync(bh, sBh + (warp_n * 64 + ni * 16) * PADH + kk * 16, PADH);
#pragma unroll
                for (int mi = 0; mi < 2; mi++) {
                    wmma::mma_sync(acc[mi][ni], ah[mi], bh, acc[mi][ni]);
                    wmma::mma_sync(acc[mi][ni], al[mi], bh, acc[mi][ni]);
                }
            }
        }
        __syncthreads();
    }

    // ---- epilogue: acc -> smem, then fused bias + residual + LayerNorm ----
    float* sOut = (float*)smem;
#pragma unroll
    for (int mi = 0; mi < 2; mi++)
#pragma unroll
        for (int ni = 0; ni < 4; ni++)
            wmma::store_matrix_sync(sOut + (warp_m * 32 + mi * 16) * LDC
                                         + warp_n * 64 + ni * 16,
                                    acc[mi][ni], LDC, wmma::mem_row_major);
    __syncthreads();

    // warp w handles rows w*8 .. w*8+7; lane owns 8 contiguous cols
#pragma unroll
    for (int rr8 = 0; rr8 < 8; rr8++) {
        int row = w * 8 + rr8;
        int grow = row0 + row;
        int c0 = lane * 8;
        float* rp = sOut + row * LDC + c0;
        float4 a0 = *(float4*)rp;
        float4 a1 = *(float4*)(rp + 4);
        const float4* xr = (const float4*)(xres + (size_t)grow * Ev + c0);
        float4 x0 = xr[0], x1 = xr[1];
        const float4* br = (const float4*)(bias + c0);
        float4 b0 = br[0], b1 = br[1];
        float v[8] = {a0.x + x0.x + b0.x, a0.y + x0.y + b0.y,
                      a0.z + x0.z + b0.z, a0.w + x0.w + b0.w,
                      a1.x + x1.x + b1.x, a1.y + x1.y + b1.y,
                      a1.z + x1.z + b1.z, a1.w + x1.w + b1.w};
        float s = 0.f, sq = 0.f;
#pragma unroll
        for (int j = 0; j < 8; j++) { s += v[j]; sq += v[j] * v[j]; }
#pragma unroll
        for (int o = 16; o; o >>= 1) {
            s  += __shfl_xor_sync(0xffffffffu, s,  o);
            sq += __shfl_xor_sync(0xffffffffu, sq, o);
        }
        float m   = s * (1.0f / Ev);
        float var = sq * (1.0f / Ev) - m * m;
        float inv = rsqrtf(var + 1e-5f);
        const float4* gr  = (const float4*)(lng + c0);
        const float4* bbr = (const float4*)(lnb + c0);
        float4 g0 = gr[0], g1 = gr[1];
        float4 lb0 = bbr[0], lb1 = bbr[1];
        float4 o0, o1;
        o0.x = (v[0] - m) * inv * g0.x + lb0.x;
        o0.y = (v[1] - m) * inv * g0.y + lb0.y;
        o0.z = (v[2] - m) * inv * g0.z + lb0.z;
        o0.w = (v[3] - m) * inv * g0.w + lb0.w;
        o1.x = (v[4] - m) * inv * g1.x + lb1.x;
        o1.y = (v[5] - m) * inv * g1.y + lb1.y;
        o1.z = (v[6] - m) * inv * g1.z + lb1.z;
        o1.w = (v[7] - m) * inv * g1.w + lb1.w;
        float4* op = (float4*)(Cout + (size_t)grow * Ev + c0);
        op[0] = o0; op[1] = o1;
    }
}

// ---------------------------------------------------------------------------
// 3. FFN hidden: h = relu( (cos(x[:, :8]) * cos(theta)) @ W1 + b1 )
//    writes pre-split fp16 hi/lo
// ---------------------------------------------------------------------------
__global__ void ffn_h_kernel(const float* __restrict__ x,
                             const float* __restrict__ ffn_theta,
                             const float* __restrict__ W1,
                             const float* __restrict__ b1,
                             __half* __restrict__ hh,
                             __half* __restrict__ hl) {
    int row0 = blockIdx.x * 8;
    int t = threadIdx.x;
    __shared__ float qs[8][NQv];
    if (t < 64) {
        int m = t >> 3, n = t & 7;
        qs[m][n] = cosf(x[(size_t)(row0 + m) * Ev + n]) * cosf(ffn_theta[n]);
    }
    __syncthreads();
#pragma unroll
    for (int fo = 0; fo < FFNv; fo += 256) {
        int f = fo + t;
        float w[NQv];
#pragma unroll
        for (int n = 0; n < NQv; n++) w[n] = W1[n * FFNv + f];
        float bb = b1[f];
#pragma unroll
        for (int m = 0; m < 8; m++) {
            float acc = bb;
#pragma unroll
            for (int n = 0; n < NQv; n++) acc = fmaf(qs[m][n], w[n], acc);
            float h = fmaxf(acc, 0.f);
            __half hi = __float2half_rn(h);
            size_t idx = (size_t)(row0 + m) * FFNv + f;
            hh[idx] = hi;
            hl[idx] = __float2half_rn(h - __half2float(hi));
        }
    }
}

// ---------------------------------------------------------------------------
// 4. pooled mean + classifier
// ---------------------------------------------------------------------------
#define POOL_SPLIT 32
__global__ void pool1_kernel(const float* __restrict__ x, float* __restrict__ part) {
    int b = blockIdx.x, sp = blockIdx.y;
    int e = threadIdx.x;
    size_t base = ((size_t)b * Sv + (size_t)sp * (Sv / POOL_SPLIT)) * Ev + e;
    float s = 0.f;
#pragma unroll 4
    for (int i = 0; i < Sv / POOL_SPLIT; i++) s += x[base + (size_t)i * Ev];
    part[((size_t)b * POOL_SPLIT + sp) * Ev + e] = s;
}

__global__ void pool2_kernel(const float* __restrict__ part,
                             const float* __restrict__ cls_w,
                             const float* __restrict__ cls_b,
                             float* __restrict__ out) {
    int b = blockIdx.x;
    int e = threadIdx.x;
    float s = 0.f;
#pragma unroll
    for (int i = 0; i < POOL_SPLIT; i++) s += part[((size_t)b * POOL_SPLIT + i) * Ev + e];
    s *= (1.0f / Sv);
    __shared__ float red[Ev];
#pragma unroll
    for (int c = 0; c < Cv; c++) {
        red[e] = s * cls_w[e * Cv + c];
        __syncthreads();
        for (int o = 128; o; o >>= 1) {
            if (e < o) red[e] += red[e + o];
            __syncthreads();
        }
        if (e == 0) out[b * Cv + c] = red[0] + cls_b[c];
        __syncthreads();
    }
}

// ---------------------------------------------------------------------------
extern "C" void kernel_launch(void* const* d_in, const int* in_sizes, int n_in,
                              void* d_out, int out_size) {
    const int*   tokens     = (const int*)  d_in[0];
    const float* embed      = (const float*)d_in[1];
    const float* attn_theta = (const float*)d_in[2];
    const float* combine_w  = (const float*)d_in[3];
    const float* combine_b  = (const float*)d_in[4];
    const float* ffn_theta  = (const float*)d_in[5];
    const float* lin1_w     = (const float*)d_in[6];
    const float* lin1_b     = (const float*)d_in[7];
    const float* lin2_w     = (const float*)d_in[8];
    const float* lin2_b     = (const float*)d_in[9];
    const float* ln1_g      = (const float*)d_in[10];
    const float* ln1_b      = (const float*)d_in[11];
    const float* ln2_g      = (const float*)d_in[12];
    const float* ln2_b      = (const float*)d_in[13];
    const float* cls_w      = (const float*)d_in[14];
    const float* cls_b      = (const float*)d_in[15];
    float* out = (float*)d_out;

    float *x, *pool;
    __half *hh, *hl, *bth;
    cudaGetSymbolAddress((void**)&x, g_x);
    cudaGetSymbolAddress((void**)&hh, g_hh);
    cudaGetSymbolAddress((void**)&hl, g_hl);
    cudaGetSymbolAddress((void**)&bth, g_bth);
    cudaGetSymbolAddress((void**)&pool, g_pool);

    cudaFuncSetAttribute(gemm_ln<0>, cudaFuncAttributeMaxDynamicSharedMemorySize, SMEM_TOT);
    cudaFuncSetAttribute(gemm_ln<1>, cudaFuncAttributeMaxDynamicSharedMemorySize, SMEM_TOT);

    embed_pos_kernel<<<(Mv * Ev + 255) / 256, 256>>>(tokens, embed, x);

    for (int l = 0; l < Lv; l++) {
        // x = LN( x + cos(x+theta)@combine_w + combine_b ) * g1 + b1
        prep_bt_kernel<<<(Ev * Ev + 255) / 256, 256>>>(
            combine_w + (size_t)l * Ev * Ev, bth, Ev);
        gemm_ln<1><<<Mv / 64, 256, SMEM_TOT>>>(
            x, (const __half*)0, (const __half*)0, bth,
            combine_b + l * Ev, attn_theta + l * 64,
            ln1_g + l * Ev, ln1_b + l * Ev, x, x, Ev);

        // h = relu(q @ lin1_w + b1), pre-split fp16
        ffn_h_kernel<<<Mv / 8, 256>>>(x, ffn_theta + l * NQv,
                                      lin1_w + (size_t)l * NQv * FFNv,
                                      lin1_b + l * FFNv, hh, hl);
        // x = LN( x + h@lin2_w + lin2_b ) * g2 + b2
        prep_bt_kernel<<<(FFNv * Ev + 255) / 256, 256>>>(
            lin2_w + (size_t)l * FFNv * Ev, bth, FFNv);
        gemm_ln<0><<<Mv / 64, 256, SMEM_TOT>>>(
            (const float*)0, hh, hl, bth,
            lin2_b + l * Ev, (const float*)0,
            ln2_g + l * Ev, ln2_b + l * Ev, x, x, FFNv);
    }

    dim3 pgrid(Bv, POOL_SPLIT);
    pool1_kernel<<<pgrid, Ev>>>(x, pool);
    pool2_kernel<<<Bv, Ev>>>(pool, cls_w, cls_b, out);
}